// round 4
// baseline (speedup 1.0000x reference)
#include <cuda_runtime.h>
#include <cstdint>

// Per-row nonlinear scan, w[k+1] = w[k] + a/w[k] - b*x[k], 32768 rows x 1024.
// One thread per row; 32x32 smem transpose tiles (pad +1 -> conflict-free).
//
// ARITHMETIC IS FROZEN: `w + a / w - b * xv` with IEEE div, default rounding.
// rcp.approx diverges (rel_err 2.05) -- some rows pass near w=0 where the map
// is chaotic. Rounds 1-2 with this exact expression gave rel_err 0.0.
//
// Round 4 structure (= round 3 pipeline, exact math restored):
//  - separate double-buffered out-tiles: tile t-1's store-out issues BEFORE
//    tile t's compute, hiding LDS+STG latency under the ~1280-cycle chain
//  - input prefetch depth 2 (LDGs issued 2 iterations ahead)
//  - one syncwarp per iteration

#define N_COLS 1024
#define WPB 4
#define TILE 32
#define NT (N_COLS / TILE)   // 32 tiles

__global__ __launch_bounds__(WPB * 32)
void DDK_77644418777662_kernel(const float* __restrict__ x,
                               const float* __restrict__ alpha,
                               const float* __restrict__ beta,
                               float* __restrict__ out,
                               int rows) {
    __shared__ float ib[2][WPB][TILE][TILE + 1];  // input tiles (double buf)
    __shared__ float ob[2][WPB][TILE][TILE + 1];  // output tiles (double buf)

    const int warp = threadIdx.x >> 5;
    const int lane = threadIdx.x & 31;
    const int rowBase = (blockIdx.x * WPB + warp) * TILE;
    if (rowBase >= rows) return;

    const float a = __ldg(alpha);
    const float b = __ldg(beta);

    const float* xrow = x + (size_t)rowBase * N_COLS;
    float* orow       = out + (size_t)rowBase * N_COLS;

    const int tr = lane >> 3;   // 0..3 row offset within 4-row group
    const int tc = lane & 7;    // 0..7 float4 index within row

    float4 pf[8];

    // ---- prologue: tile 0 -> ib[0]; tile 1 LDGs left in flight ----
    #pragma unroll
    for (int g = 0; g < 8; g++)
        pf[g] = *(const float4*)(xrow + (size_t)(g * 4 + tr) * N_COLS + tc * 4);
    #pragma unroll
    for (int g = 0; g < 8; g++) {
        const int r = g * 4 + tr;
        ib[0][warp][r][tc * 4 + 0] = pf[g].x;
        ib[0][warp][r][tc * 4 + 1] = pf[g].y;
        ib[0][warp][r][tc * 4 + 2] = pf[g].z;
        ib[0][warp][r][tc * 4 + 3] = pf[g].w;
    }
    __syncwarp();
    #pragma unroll
    for (int g = 0; g < 8; g++)
        pf[g] = *(const float4*)(xrow + (size_t)(g * 4 + tr) * N_COLS + TILE + tc * 4);

    float w = 1.0f;

    #pragma unroll 2
    for (int t = 0; t < NT; t++) {
        const int buf = t & 1;

        // commit prefetched tile t+1 into the idle input buffer
        if (t + 1 < NT) {
            #pragma unroll
            for (int g = 0; g < 8; g++) {
                const int r = g * 4 + tr;
                ib[buf ^ 1][warp][r][tc * 4 + 0] = pf[g].x;
                ib[buf ^ 1][warp][r][tc * 4 + 1] = pf[g].y;
                ib[buf ^ 1][warp][r][tc * 4 + 2] = pf[g].z;
                ib[buf ^ 1][warp][r][tc * 4 + 3] = pf[g].w;
            }
        }
        // issue LDGs for tile t+2 (two iterations of flight time)
        if (t + 2 < NT) {
            const int c0 = (t + 2) * TILE;
            #pragma unroll
            for (int g = 0; g < 8; g++)
                pf[g] = *(const float4*)(xrow + (size_t)(g * 4 + tr) * N_COLS
                                         + c0 + tc * 4);
        }
        // store-out tile t-1 (reads ob[buf^1]; latency hides under compute)
        if (t >= 1) {
            const int c0 = (t - 1) * TILE;
            #pragma unroll
            for (int g = 0; g < 8; g++) {
                const int r = g * 4 + tr;
                float4 v;
                v.x = ob[buf ^ 1][warp][r][tc * 4 + 0];
                v.y = ob[buf ^ 1][warp][r][tc * 4 + 1];
                v.z = ob[buf ^ 1][warp][r][tc * 4 + 2];
                v.w = ob[buf ^ 1][warp][r][tc * 4 + 3];
                *(float4*)(orow + (size_t)r * N_COLS + c0 + tc * 4) = v;
            }
        }

        // ---- 32 sequential steps, EXACT reference arithmetic ----
        // out[k] = w (pre-update). Final update of the last tile is dead code.
        #pragma unroll
        for (int j = 0; j < TILE; j++) {
            const float xv = ib[buf][warp][lane][j];
            ob[buf][warp][lane][j] = w;
            w = w + a / w - b * xv;       // FROZEN: bitwise-matching expression
        }
        __syncwarp();
    }

    // ---- epilogue: store-out the last tile ----
    {
        const int c0 = (NT - 1) * TILE;
        const int buf = (NT - 1) & 1;
        #pragma unroll
        for (int g = 0; g < 8; g++) {
            const int r = g * 4 + tr;
            float4 v;
            v.x = ob[buf][warp][r][tc * 4 + 0];
            v.y = ob[buf][warp][r][tc * 4 + 1];
            v.z = ob[buf][warp][r][tc * 4 + 2];
            v.w = ob[buf][warp][r][tc * 4 + 3];
            *(float4*)(orow + (size_t)r * N_COLS + c0 + tc * 4) = v;
        }
    }
}

extern "C" void kernel_launch(void* const* d_in, const int* in_sizes, int n_in,
                              void* d_out, int out_size) {
    const float* x     = (const float*)d_in[0];
    const float* alpha = (const float*)d_in[1];
    const float* beta  = (const float*)d_in[2];
    float* out         = (float*)d_out;

    const int rows = out_size / N_COLS;                    // 32768
    const int rowsPerBlock = WPB * TILE;                   // 128
    const int blocks = (rows + rowsPerBlock - 1) / rowsPerBlock;  // 256

    DDK_77644418777662_kernel<<<blocks, WPB * 32>>>(x, alpha, beta, out, rows);
}